// round 8
// baseline (speedup 1.0000x reference)
#include <cuda_runtime.h>
#include <cstdint>

#define N_NODES  100000
#define N_EDGES  1600000
#define D        128
#define N_LAYERS 7
#define N_GRAPHS 64
#define N_CLASSES 10
#define SNN_IN   512
#define SNN_HID  1024
#define SNN_BETA 0.85f

// ---------------- scratch (no allocations allowed) ----------------
__device__ float g_h0[N_NODES * D];
__device__ float g_h1[N_NODES * D];
__device__ int   g_counts[N_NODES];
__device__ int   g_rowptr[N_NODES + 1];
__device__ int   g_wptr[N_NODES];
__device__ int   g_esrc[N_EDGES];
__device__ int   g_blocksums[256];
__device__ float g_pool[N_GRAPHS * D];
__device__ float g_cnt[N_GRAPHS];
__device__ float g_snnh[N_GRAPHS * SNN_HID];
__device__ int   g_flags[2];   // [0]: edge_index is int64, [1]: batch is int64
// packed bf16x2 split weights: [l][mat][part][n][kword]  (2 k per word)
__device__ uint32_t g_wsp[N_LAYERS * 2 * 2 * D * (D / 2)];

// ---------------- portable tensor-core helpers (sm_80+ ISA only) ----------------
__device__ __forceinline__ uint32_t pack_bf16(float lo, float hi) {
    uint32_t r;
    asm("cvt.rn.bf16x2.f32 %0, %1, %2;" : "=r"(r) : "f"(hi), "f"(lo));
    return r;
}
__device__ __forceinline__ void mma_bf16(float* d, const uint32_t* a, uint32_t b0, uint32_t b1) {
    asm volatile(
        "mma.sync.aligned.m16n8k16.row.col.f32.bf16.bf16.f32 "
        "{%0,%1,%2,%3}, {%4,%5,%6,%7}, {%8,%9}, {%0,%1,%2,%3};"
        : "+f"(d[0]), "+f"(d[1]), "+f"(d[2]), "+f"(d[3])
        : "r"(a[0]), "r"(a[1]), "r"(a[2]), "r"(a[3]), "r"(b0), "r"(b1));
}
__device__ __forceinline__ void ldsm_x4(uint32_t* r, uint32_t addr) {
    asm volatile("ldmatrix.sync.aligned.m8n8.x4.shared.b16 {%0,%1,%2,%3}, [%4];"
        : "=r"(r[0]), "=r"(r[1]), "=r"(r[2]), "=r"(r[3]) : "r"(addr));
}
__device__ __forceinline__ void ldsm_x2(uint32_t* r, uint32_t addr) {
    asm volatile("ldmatrix.sync.aligned.m8n8.x2.shared.b16 {%0,%1}, [%2];"
        : "=r"(r[0]), "=r"(r[1]) : "r"(addr));
}
__device__ __forceinline__ uint32_t smem_u32(const void* p) {
    uint32_t a;
    asm("{ .reg .u64 t; cvta.to.shared.u64 t, %1; cvt.u32.u64 %0, t; }" : "=r"(a) : "l"(p));
    return a;
}
// split two floats into packed bf16 hi word + residual lo word
__device__ __forceinline__ void split2(float f0, float f1, uint32_t& hw, uint32_t& lw) {
    hw = pack_bf16(f0, f1);
    float f0h = __uint_as_float(hw << 16);
    float f1h = __uint_as_float(hw & 0xFFFF0000u);
    lw = pack_bf16(f0 - f0h, f1 - f1h);
}

// ---------------- index-width helpers ----------------
__device__ __forceinline__ int ld_idx(const void* p, long long i, int is64) {
    if (is64) return (int)((const long long*)p)[i];
    return ((const int*)p)[i];
}

// Parallel dtype detection
__global__ void k_detect(const unsigned int* ei, const unsigned int* bt) {
    __shared__ int e64s, b64s;
    int t = threadIdx.x;   // 256
    if (t == 0) { e64s = 1; b64s = 1; }
    __syncthreads();
    if (ei[2 * t + 1] != 0u) e64s = 0;
    if (bt[99999 - 2 * t] != 0u) b64s = 0;
    __syncthreads();
    if (t == 0) { g_flags[0] = e64s; g_flags[1] = b64s; }
}

// Transpose + bf16 hi/lo split of all layer weights, packed 2-k-per-word.
__global__ void k_wprep(const float* __restrict__ wrel, const float* __restrict__ wroot) {
    int idx = blockIdx.x * 256 + threadIdx.x;
    const int WORDS = N_LAYERS * 2 * D * (D / 2);   // 114688
    if (idx >= WORDS) return;
    int l = idx >> 14;
    int rem = idx & 16383;
    int mat = rem >> 13;
    int r2 = rem & 8191;
    int n = r2 >> 6;
    int wk = r2 & 63;
    int k = wk * 2;
    const float* W = (mat ? wroot : wrel) + (long long)l * D * D;
    float f0 = W[k * D + n];
    float f1 = W[(k + 1) * D + n];
    uint32_t hw, lw;
    split2(f0, f1, hw, lw);
    int base = ((l * 2 + mat) * 2) * 8192 + n * 64 + wk;
    g_wsp[base] = hw;
    g_wsp[base + 8192] = lw;
}

// ---------------- CSR build ----------------
__global__ void k_zero_counts() {
    int i = blockIdx.x * blockDim.x + threadIdx.x;
    if (i < N_NODES) g_counts[i] = 0;
}
__global__ void k_hist(const void* ei) {
    int e = blockIdx.x * blockDim.x + threadIdx.x;
    if (e >= N_EDGES) return;
    int dst = ld_idx(ei, (long long)N_EDGES + e, g_flags[0]);
    atomicAdd(&g_counts[dst], 1);
}
__global__ void k_scan1() {
    __shared__ int s[1024];
    int blk = blockIdx.x, t = threadIdx.x;
    int idx = blk * 1024 + t;
    int v = (idx < N_NODES) ? g_counts[idx] : 0;
    s[t] = v;
    __syncthreads();
    for (int off = 1; off < 1024; off <<= 1) {
        int add = (t >= off) ? s[t - off] : 0;
        __syncthreads();
        s[t] += add;
        __syncthreads();
    }
    if (idx < N_NODES) g_rowptr[idx] = s[t];
    if (t == 1023) g_blocksums[blk] = s[t];
}
__global__ void k_scan2(int nblocks) {
    if (blockIdx.x == 0 && threadIdx.x == 0) {
        int acc = 0;
        for (int b = 0; b < nblocks; b++) { int v = g_blocksums[b]; g_blocksums[b] = acc; acc += v; }
        g_rowptr[N_NODES] = N_EDGES;
    }
}
__global__ void k_scan3() {
    int i = blockIdx.x * blockDim.x + threadIdx.x;
    if (i < N_NODES) {
        int ex = g_rowptr[i] - g_counts[i] + g_blocksums[i >> 10];
        g_rowptr[i] = ex;
        g_wptr[i] = ex;
    }
}
__global__ void k_scatter(const void* ei) {
    int e = blockIdx.x * blockDim.x + threadIdx.x;
    if (e >= N_EDGES) return;
    int is64 = g_flags[0];
    int src = ld_idx(ei, e, is64);
    int dst = ld_idx(ei, (long long)N_EDGES + e, is64);
    int pos = atomicAdd(&g_wptr[dst], 1);
    g_esrc[pos] = src;
}

// ---------------- fused GraphConv layer: gather + 3xBF16 mma GEMM ----------------
// out[m,:] = relu( (sum_{j->m} h[j,:]) @ W1 + h[m,:] @ W2 + bias )
// CTA = 128 M-rows. Phase 1: warp-per-node gather of agg rows, bf16-split into
// full-K SMEM tiles (272B row stride -> ldmatrix conflict-free, 272/16=17 odd).
// Phase 2: 8 x 32-K mma chunks; c<4 use agg tiles, c>=4 stage h chunks from gmem.
#define KSTR 272
#define RSTR 80
#define SM_AGH 0
#define SM_AGL 34816
#define SM_BH  69632
#define SM_BL  79872
#define SM_HH  90112
#define SM_HL  100352
#define LAYER_SMEM 110592

__global__ __launch_bounds__(256, 2)
void k_layer(const float* __restrict__ h,
             const uint32_t* __restrict__ Wt,   // layer base: 4 tiles of 8192 words
             const float* __restrict__ bias, float* __restrict__ C) {
    extern __shared__ __align__(16) char smc[];
    const uint32_t sbase = smem_u32(smc);
    const int tid = threadIdx.x;
    const int w = tid >> 5;
    const int lane = tid & 31;
    const int g = lane >> 2;
    const int tg = lane & 3;
    const int bm = blockIdx.x * 128;
    const int mbase = (w & 3) * 32;
    const int nbase = (w >> 2) * 64;

    const int srow = tid >> 3;          // staging row 0..31 (+32/it)
    const int sq = tid & 7;             // k-quad

    // ---- prefetch h chunk c=4 early (global latency hidden under gather) ----
    float4 pa[4];
#pragma unroll
    for (int it = 0; it < 4; it++) {
        int row = it * 32 + srow;
        pa[it] = (bm + row < N_NODES)
                 ? *(const float4*)&h[(long long)(bm + row) * 128 + sq * 4]
                 : make_float4(0.f, 0.f, 0.f, 0.f);
    }

    // ---- phase 1: gather agg rows into full-K split SMEM tiles ----
#pragma unroll 1
    for (int i = 0; i < 16; i++) {
        int lrow = w * 16 + i;
        int node = bm + lrow;
        float4 acc = make_float4(0.f, 0.f, 0.f, 0.f);
        if (node < N_NODES) {
            int s = g_rowptr[node];
            int e = g_rowptr[node + 1];
            for (int j = s; j < e; j++) {
                int src = g_esrc[j];
                float4 v = *(const float4*)&h[(long long)src * 128 + lane * 4];
                acc.x += v.x; acc.y += v.y; acc.z += v.z; acc.w += v.w;
            }
        }
        uint32_t h01, l01, h23, l23;
        split2(acc.x, acc.y, h01, l01);
        split2(acc.z, acc.w, h23, l23);
        uint32_t off = (uint32_t)(lrow * KSTR + lane * 8);
        *(uint2*)(smc + SM_AGH + off) = make_uint2(h01, h23);
        *(uint2*)(smc + SM_AGL + off) = make_uint2(l01, l23);
    }

    float acc[2][8][4];
#pragma unroll
    for (int mt = 0; mt < 2; mt++)
#pragma unroll
        for (int nt = 0; nt < 8; nt++)
#pragma unroll
            for (int q = 0; q < 4; q++) acc[mt][nt][q] = 0.f;

    // ldmatrix lane addressing
    const int aRow16 = lane & 15;
    const uint32_t aSel = (uint32_t)(lane >> 4) * 16u;
    const int bRow = lane & 7;
    const uint32_t bK = (uint32_t)((lane >> 3) & 1) * 16u;

    // ---- chunks 0..3: agg @ W1 (A already in SMEM full-K tiles) ----
#pragma unroll
    for (int c = 0; c < 4; c++) {
        const int k0w = c * 16;
        const uint32_t* Whi = Wt;            // W1 hi tile
        const uint32_t* Wlo = Wt + 8192;     // W1 lo tile
#pragma unroll
        for (int it = 0; it < 4; it++) {
            int row = it * 32 + srow;
            uint32_t off = (uint32_t)(row * RSTR + sq * 8);
            *(uint2*)(smc + SM_BH + off) = *(const uint2*)&Whi[row * 64 + k0w + sq * 2];
            *(uint2*)(smc + SM_BL + off) = *(const uint2*)&Wlo[row * 64 + k0w + sq * 2];
        }
        __syncthreads();
#pragma unroll
        for (int ks = 0; ks < 2; ks++) {
            uint32_t ah[2][4], al[2][4];
#pragma unroll
            for (int mt = 0; mt < 2; mt++) {
                uint32_t base = sbase + (uint32_t)((mbase + mt * 16 + aRow16) * KSTR)
                              + (uint32_t)(c * 64 + ks * 32) + aSel;
                ldsm_x4(ah[mt], base + SM_AGH);
                ldsm_x4(al[mt], base + SM_AGL);
            }
#pragma unroll
            for (int nt = 0; nt < 8; nt++) {
                uint32_t bb = sbase + (uint32_t)((nbase + nt * 8 + bRow) * RSTR)
                            + (uint32_t)ks * 32u + bK;
                uint32_t bh[2], bl[2];
                ldsm_x2(bh, bb + SM_BH);
                ldsm_x2(bl, bb + SM_BL);
#pragma unroll
                for (int mt = 0; mt < 2; mt++) {
                    mma_bf16(acc[mt][nt], ah[mt], bh[0], bh[1]);
                    mma_bf16(acc[mt][nt], ah[mt], bl[0], bl[1]);
                    mma_bf16(acc[mt][nt], al[mt], bh[0], bh[1]);
                }
            }
        }
        __syncthreads();
    }

    // ---- chunks 4..7: h @ W2 (stage h chunks with register prefetch) ----
#pragma unroll
    for (int c = 4; c < 8; c++) {
        const int k0w = (c & 3) * 16;
        const uint32_t* Whi = Wt + 2 * 8192;   // W2 hi
        const uint32_t* Wlo = Wt + 3 * 8192;   // W2 lo
#pragma unroll
        for (int it = 0; it < 4; it++) {
            int row = it * 32 + srow;
            uint32_t off = (uint32_t)(row * RSTR + sq * 8);
            float4 v = pa[it];
            uint32_t h01, l01, h23, l23;
            split2(v.x, v.y, h01, l01);
            split2(v.z, v.w, h23, l23);
            *(uint2*)(smc + SM_HH + off) = make_uint2(h01, h23);
            *(uint2*)(smc + SM_HL + off) = make_uint2(l01, l23);
            *(uint2*)(smc + SM_BH + off) = *(const uint2*)&Whi[row * 64 + k0w + sq * 2];
            *(uint2*)(smc + SM_BL + off) = *(const uint2*)&Wlo[row * 64 + k0w + sq * 2];
        }
        __syncthreads();
        if (c < 7) {
            const int k0n = ((c + 1) & 3) * 32;
#pragma unroll
            for (int it = 0; it < 4; it++) {
                int row = it * 32 + srow;
                pa[it] = (bm + row < N_NODES)
                         ? *(const float4*)&h[(long long)(bm + row) * 128 + k0n + sq * 4]
                         : make_float4(0.f, 0.f, 0.f, 0.f);
            }
        }
#pragma unroll
        for (int ks = 0; ks < 2; ks++) {
            uint32_t ah[2][4], al[2][4];
#pragma unroll
            for (int mt = 0; mt < 2; mt++) {
                uint32_t base = sbase + (uint32_t)((mbase + mt * 16 + aRow16) * RSTR)
                              + (uint32_t)ks * 32u + aSel;
                ldsm_x4(ah[mt], base + SM_HH);
                ldsm_x4(al[mt], base + SM_HL);
            }
#pragma unroll
            for (int nt = 0; nt < 8; nt++) {
                uint32_t bb = sbase + (uint32_t)((nbase + nt * 8 + bRow) * RSTR)
                            + (uint32_t)ks * 32u + bK;
                uint32_t bh[2], bl[2];
                ldsm_x2(bh, bb + SM_BH);
                ldsm_x2(bl, bb + SM_BL);
#pragma unroll
                for (int mt = 0; mt < 2; mt++) {
                    mma_bf16(acc[mt][nt], ah[mt], bh[0], bh[1]);
                    mma_bf16(acc[mt][nt], ah[mt], bl[0], bl[1]);
                    mma_bf16(acc[mt][nt], al[mt], bh[0], bh[1]);
                }
            }
        }
        __syncthreads();
    }

    // ---- epilogue: bias + relu, float2 stores ----
#pragma unroll
    for (int mt = 0; mt < 2; mt++) {
        int row0 = bm + mbase + mt * 16 + g;
        int row1 = row0 + 8;
#pragma unroll
        for (int nt = 0; nt < 8; nt++) {
            int col = nbase + nt * 8 + 2 * tg;
            float b0 = bias[col];
            float b1 = bias[col + 1];
            if (row0 < N_NODES) {
                float2 o;
                o.x = fmaxf(acc[mt][nt][0] + b0, 0.f);
                o.y = fmaxf(acc[mt][nt][1] + b1, 0.f);
                *(float2*)&C[(long long)row0 * 128 + col] = o;
            }
            if (row1 < N_NODES) {
                float2 o;
                o.x = fmaxf(acc[mt][nt][2] + b0, 0.f);
                o.y = fmaxf(acc[mt][nt][3] + b1, 0.f);
                *(float2*)&C[(long long)row1 * 128 + col] = o;
            }
        }
    }
}

// ---------------- pooling / SNN / fusion ----------------
__global__ void k_zero_pool() {
    int i = blockIdx.x * blockDim.x + threadIdx.x;
    if (i < N_GRAPHS * D) g_pool[i] = 0.f;
    if (i < N_GRAPHS) g_cnt[i] = 0.f;
}

#define PCHUNK 256
__global__ void k_pool(const float* __restrict__ h, const void* bt) {
    int blk = blockIdx.x;
    int f = threadIdx.x;
    int start = blk * PCHUNK;
    if (start >= N_NODES) return;
    int end = start + PCHUNK;
    if (end > N_NODES) end = N_NODES;
    int is64 = g_flags[1];
    int cur = ld_idx(bt, start, is64);
    float s = 0.f, c = 0.f;
    for (int n = start; n < end; n++) {
        int g = ld_idx(bt, n, is64);
        if (g != cur) {
            atomicAdd(&g_pool[cur * D + f], s);
            if (f == 0) atomicAdd(&g_cnt[cur], c);
            s = 0.f; c = 0.f; cur = g;
        }
        s += h[(long long)n * D + f];
        c += 1.f;
    }
    atomicAdd(&g_pool[cur * D + f], s);
    if (f == 0) atomicAdd(&g_cnt[cur], c);
}

__global__ void k_snn1(const float* __restrict__ x, const float* __restrict__ w1,
                       const float* __restrict__ b1) {
    int g = blockIdx.x;
    int t = threadIdx.x;   // 256
    __shared__ float xs[SNN_IN];
    for (int i = t; i < SNN_IN; i += 256) xs[i] = x[g * SNN_IN + i];
    __syncthreads();
    for (int j = t; j < SNN_HID; j += 256) {
        float a = b1[j];
        for (int k = 0; k < SNN_IN; k++)
            a += xs[k] * w1[k * SNN_HID + j];
        g_snnh[g * SNN_HID + j] = fmaxf(a, 0.f);
    }
}

__global__ void k_final(const float* __restrict__ lin_w, const float* __restrict__ lin_b,
                        const float* __restrict__ w2, const float* __restrict__ b2,
                        const float* __restrict__ fuse_w, const float* __restrict__ fuse_b,
                        float* __restrict__ out) {
    int g = blockIdx.x;
    int t = threadIdx.x;   // 128
    __shared__ float mean[D];
    __shared__ float red[128];
    __shared__ float snl[N_CLASSES], gnl[N_CLASSES];
    float cnt = fmaxf(g_cnt[g], 1.f);
    mean[t] = g_pool[g * D + t] / cnt;
    __syncthreads();
    for (int c = 0; c < N_CLASSES; c++) {
        red[t] = mean[t] * lin_w[t * N_CLASSES + c];
        for (int off = 64; off > 0; off >>= 1) {
            __syncthreads();
            if (t < off) red[t] += red[t + off];
        }
        __syncthreads();
        if (t == 0) gnl[c] = red[0] + lin_b[c];
        __syncthreads();
    }
    for (int c = 0; c < N_CLASSES; c++) {
        float p = 0.f;
        for (int k = t; k < SNN_HID; k += 128)
            p += g_snnh[g * SNN_HID + k] * w2[k * N_CLASSES + c];
        red[t] = p;
        for (int off = 64; off > 0; off >>= 1) {
            __syncthreads();
            if (t < off) red[t] += red[t + off];
        }
        __syncthreads();
        if (t == 0) snl[c] = SNN_BETA * (red[0] + b2[c]);
        __syncthreads();
    }
    if (t < N_CLASSES) {
        float o = fuse_b[t];
        for (int j = 0; j < N_CLASSES; j++) {
            o += snl[j] * fuse_w[j * N_CLASSES + t];
            o += gnl[j] * fuse_w[(N_CLASSES + j) * N_CLASSES + t];
        }
        out[g * N_CLASSES + t] = o;
    }
}

// ---------------- launch ----------------
extern "C" void kernel_launch(void* const* d_in, const int* in_sizes, int n_in,
                              void* d_out, int out_size) {
    const float* snn_x  = (const float*)d_in[0];
    const float* x      = (const float*)d_in[1];
    const void*  ei     = d_in[2];
    const void*  bt     = d_in[3];
    const float* snn_w1 = (const float*)d_in[4];
    const float* snn_b1 = (const float*)d_in[5];
    const float* snn_w2 = (const float*)d_in[6];
    const float* snn_b2 = (const float*)d_in[7];
    const float* wrel   = (const float*)d_in[8];
    const float* wroot  = (const float*)d_in[9];
    const float* brel   = (const float*)d_in[10];
    const float* lin_w  = (const float*)d_in[11];
    const float* lin_b  = (const float*)d_in[12];
    const float* fuse_w = (const float*)d_in[13];
    const float* fuse_b = (const float*)d_in[14];
    float* out = (float*)d_out;

    void* p;
    cudaGetSymbolAddress(&p, g_h0);   float* h0  = (float*)p;
    cudaGetSymbolAddress(&p, g_h1);   float* h1  = (float*)p;
    cudaGetSymbolAddress(&p, g_wsp);  uint32_t* wsp = (uint32_t*)p;

    cudaFuncSetAttribute(k_layer, cudaFuncAttributeMaxDynamicSharedMemorySize, LAYER_SMEM);

    k_detect<<<1, 256>>>((const unsigned int*)ei, (const unsigned int*)bt);
    k_wprep<<<(N_LAYERS * 2 * D * (D / 2) + 255) / 256, 256>>>(wrel, wroot);

    // CSR build (by dst)
    k_zero_counts<<<(N_NODES + 255) / 256, 256>>>();
    k_hist<<<(N_EDGES + 255) / 256, 256>>>(ei);
    const int nsb = (N_NODES + 1023) / 1024;   // 98
    k_scan1<<<nsb, 1024>>>();
    k_scan2<<<1, 1>>>(nsb);
    k_scan3<<<(N_NODES + 255) / 256, 256>>>();
    k_scatter<<<(N_EDGES + 255) / 256, 256>>>(ei);

    // 7 fused GraphConv layers; layer 0 consumes x directly
    const float* hin = x;
    float* hout = h1;
    const int layerBlocks = (N_NODES + 127) / 128;   // 782
    for (int l = 0; l < N_LAYERS; l++) {
        k_layer<<<layerBlocks, 256, LAYER_SMEM>>>(hin,
                                                  wsp + (long long)l * 4 * 8192,
                                                  brel + (long long)l * D, hout);
        hin = hout;
        hout = (hout == h1) ? h0 : h1;
    }

    // global mean pool
    k_zero_pool<<<(N_GRAPHS * D + 255) / 256, 256>>>();
    k_pool<<<(N_NODES + PCHUNK - 1) / PCHUNK, 128>>>(hin, bt);

    // SNN + fusion
    k_snn1<<<N_GRAPHS, 256>>>(snn_x, snn_w1, snn_b1);
    k_final<<<N_GRAPHS, 128>>>(lin_w, lin_b, snn_w2, snn_b2, fuse_w, fuse_b, out);
}

// round 9
// speedup vs baseline: 1.3240x; 1.3240x over previous
#include <cuda_runtime.h>
#include <cstdint>

#define N_NODES  100000
#define N_EDGES  1600000
#define D        128
#define N_LAYERS 7
#define N_GRAPHS 64
#define N_CLASSES 10
#define SNN_IN   512
#define SNN_HID  1024
#define SNN_BETA 0.85f

// ---------------- scratch (no allocations allowed) ----------------
__device__ float g_h0[N_NODES * D];
__device__ float g_h1[N_NODES * D];
__device__ float g_agg[N_NODES * D];
__device__ int   g_counts[N_NODES];
__device__ int   g_rowptr[N_NODES + 1];
__device__ int   g_wptr[N_NODES];
__device__ int   g_esrc[N_EDGES];
__device__ int   g_blocksums[256];
__device__ float g_pool[N_GRAPHS * D];
__device__ float g_cnt[N_GRAPHS];
__device__ float g_snnh[N_GRAPHS * SNN_HID];
__device__ int   g_flags[2];   // [0]: edge_index is int64, [1]: batch is int64
// packed bf16x2 split weights: [l][mat][part][n][kword]  (2 k per word)
__device__ uint32_t g_wsp[N_LAYERS * 2 * 2 * D * (D / 2)];

// ---------------- portable tensor-core helpers (sm_80+ ISA only) ----------------
__device__ __forceinline__ uint32_t pack_bf16(float lo, float hi) {
    uint32_t r;
    asm("cvt.rn.bf16x2.f32 %0, %1, %2;" : "=r"(r) : "f"(hi), "f"(lo));
    return r;
}
__device__ __forceinline__ void mma_bf16(float* d, const uint32_t* a, uint32_t b0, uint32_t b1) {
    asm volatile(
        "mma.sync.aligned.m16n8k16.row.col.f32.bf16.bf16.f32 "
        "{%0,%1,%2,%3}, {%4,%5,%6,%7}, {%8,%9}, {%0,%1,%2,%3};"
        : "+f"(d[0]), "+f"(d[1]), "+f"(d[2]), "+f"(d[3])
        : "r"(a[0]), "r"(a[1]), "r"(a[2]), "r"(a[3]), "r"(b0), "r"(b1));
}
__device__ __forceinline__ void ldsm_x4(uint32_t* r, uint32_t addr) {
    asm volatile("ldmatrix.sync.aligned.m8n8.x4.shared.b16 {%0,%1,%2,%3}, [%4];"
        : "=r"(r[0]), "=r"(r[1]), "=r"(r[2]), "=r"(r[3]) : "r"(addr));
}
__device__ __forceinline__ void ldsm_x2(uint32_t* r, uint32_t addr) {
    asm volatile("ldmatrix.sync.aligned.m8n8.x2.shared.b16 {%0,%1}, [%2];"
        : "=r"(r[0]), "=r"(r[1]) : "r"(addr));
}
__device__ __forceinline__ uint32_t smem_u32(const void* p) {
    uint32_t a;
    asm("{ .reg .u64 t; cvta.to.shared.u64 t, %1; cvt.u32.u64 %0, t; }" : "=r"(a) : "l"(p));
    return a;
}
// split two floats into packed bf16 hi word + residual lo word
__device__ __forceinline__ void split2(float f0, float f1, uint32_t& hw, uint32_t& lw) {
    hw = pack_bf16(f0, f1);
    float f0h = __uint_as_float(hw << 16);
    float f1h = __uint_as_float(hw & 0xFFFF0000u);
    lw = pack_bf16(f0 - f0h, f1 - f1h);
}

// ---------------- index-width helpers ----------------
__device__ __forceinline__ int ld_idx(const void* p, long long i, int is64) {
    if (is64) return (int)((const long long*)p)[i];
    return ((const int*)p)[i];
}

// Parallel dtype detection
__global__ void k_detect(const unsigned int* ei, const unsigned int* bt) {
    __shared__ int e64s, b64s;
    int t = threadIdx.x;   // 256
    if (t == 0) { e64s = 1; b64s = 1; }
    __syncthreads();
    if (ei[2 * t + 1] != 0u) e64s = 0;
    if (bt[99999 - 2 * t] != 0u) b64s = 0;
    __syncthreads();
    if (t == 0) { g_flags[0] = e64s; g_flags[1] = b64s; }
}

// Transpose + bf16 hi/lo split of all layer weights, packed 2-k-per-word.
__global__ void k_wprep(const float* __restrict__ wrel, const float* __restrict__ wroot) {
    int idx = blockIdx.x * 256 + threadIdx.x;
    const int WORDS = N_LAYERS * 2 * D * (D / 2);   // 114688
    if (idx >= WORDS) return;
    int l = idx >> 14;
    int rem = idx & 16383;
    int mat = rem >> 13;
    int r2 = rem & 8191;
    int n = r2 >> 6;
    int wk = r2 & 63;
    int k = wk * 2;
    const float* W = (mat ? wroot : wrel) + (long long)l * D * D;
    float f0 = W[k * D + n];
    float f1 = W[(k + 1) * D + n];
    uint32_t hw, lw;
    split2(f0, f1, hw, lw);
    int base = ((l * 2 + mat) * 2) * 8192 + n * 64 + wk;
    g_wsp[base] = hw;
    g_wsp[base + 8192] = lw;
}

// ---------------- CSR build ----------------
__global__ void k_zero_counts() {
    int i = blockIdx.x * blockDim.x + threadIdx.x;
    if (i < N_NODES) g_counts[i] = 0;
}
__global__ void k_hist(const void* ei) {
    int e = blockIdx.x * blockDim.x + threadIdx.x;
    if (e >= N_EDGES) return;
    int dst = ld_idx(ei, (long long)N_EDGES + e, g_flags[0]);
    atomicAdd(&g_counts[dst], 1);
}
__global__ void k_scan1() {
    __shared__ int s[1024];
    int blk = blockIdx.x, t = threadIdx.x;
    int idx = blk * 1024 + t;
    int v = (idx < N_NODES) ? g_counts[idx] : 0;
    s[t] = v;
    __syncthreads();
    for (int off = 1; off < 1024; off <<= 1) {
        int add = (t >= off) ? s[t - off] : 0;
        __syncthreads();
        s[t] += add;
        __syncthreads();
    }
    if (idx < N_NODES) g_rowptr[idx] = s[t];
    if (t == 1023) g_blocksums[blk] = s[t];
}
__global__ void k_scan2(int nblocks) {
    if (blockIdx.x == 0 && threadIdx.x == 0) {
        int acc = 0;
        for (int b = 0; b < nblocks; b++) { int v = g_blocksums[b]; g_blocksums[b] = acc; acc += v; }
        g_rowptr[N_NODES] = N_EDGES;
    }
}
__global__ void k_scan3() {
    int i = blockIdx.x * blockDim.x + threadIdx.x;
    if (i < N_NODES) {
        int ex = g_rowptr[i] - g_counts[i] + g_blocksums[i >> 10];
        g_rowptr[i] = ex;
        g_wptr[i] = ex;
    }
}
__global__ void k_scatter(const void* ei) {
    int e = blockIdx.x * blockDim.x + threadIdx.x;
    if (e >= N_EDGES) return;
    int is64 = g_flags[0];
    int src = ld_idx(ei, e, is64);
    int dst = ld_idx(ei, (long long)N_EDGES + e, is64);
    int pos = atomicAdd(&g_wptr[dst], 1);
    g_esrc[pos] = src;
}

// ---------------- aggregation: one warp per node, 2-way unrolled edge loop ----
__global__ void k_agg(const float* __restrict__ h, float* __restrict__ agg) {
    int warp = (blockIdx.x * blockDim.x + threadIdx.x) >> 5;
    int lane = threadIdx.x & 31;
    if (warp >= N_NODES) return;
    int s = g_rowptr[warp];
    int e = g_rowptr[warp + 1];
    float4 a0 = make_float4(0.f, 0.f, 0.f, 0.f);
    float4 a1 = make_float4(0.f, 0.f, 0.f, 0.f);
    int i = s;
    for (; i + 1 < e; i += 2) {
        int s0 = g_esrc[i];
        int s1 = g_esrc[i + 1];
        float4 v0 = *(const float4*)&h[(long long)s0 * D + lane * 4];
        float4 v1 = *(const float4*)&h[(long long)s1 * D + lane * 4];
        a0.x += v0.x; a0.y += v0.y; a0.z += v0.z; a0.w += v0.w;
        a1.x += v1.x; a1.y += v1.y; a1.z += v1.z; a1.w += v1.w;
    }
    if (i < e) {
        int s0 = g_esrc[i];
        float4 v0 = *(const float4*)&h[(long long)s0 * D + lane * 4];
        a0.x += v0.x; a0.y += v0.y; a0.z += v0.z; a0.w += v0.w;
    }
    a0.x += a1.x; a0.y += a1.y; a0.z += a1.z; a0.w += a1.w;
    *(float4*)&agg[(long long)warp * D + lane * 4] = a0;
}

// ---------------- 3xBF16 mma.sync GraphConv GEMM (double-buffered) ----------------
// C[m,:] = relu( A1[m,:] @ W1 + A2[m,:] @ W2 + bias )
// CTA tile 128x128; K = 2x128 in 8 chunks of 32. Two SMEM buffers of 40KB:
// stage chunk c+1 into buf[nxt] (A from register prefetch, B from hot L1/L2),
// then compute chunk c from buf[cur]; ONE sync per chunk.
#define RSTR 80
#define SM_AH 0
#define SM_AL 10240
#define SM_BH 20480
#define SM_BL 30720
#define BUFSZ 40960
#define GEMM_SMEM (2 * BUFSZ)

__global__ __launch_bounds__(256, 2)
void k_gemm_bf16(const float* __restrict__ A1, const float* __restrict__ A2,
                 const uint32_t* __restrict__ Wt,   // layer base: 4 tiles of 8192 words
                 const float* __restrict__ bias, float* __restrict__ C) {
    extern __shared__ __align__(16) char smc[];
    const uint32_t sbase = smem_u32(smc);
    const int tid = threadIdx.x;
    const int w = tid >> 5;
    const int lane = tid & 31;
    const int g = lane >> 2;
    const int tg = lane & 3;
    const int bm = blockIdx.x * 128;
    const int mbase = (w & 3) * 32;
    const int nbase = (w >> 2) * 64;

    float acc[2][8][4];
#pragma unroll
    for (int mt = 0; mt < 2; mt++)
#pragma unroll
        for (int nt = 0; nt < 8; nt++)
#pragma unroll
            for (int q = 0; q < 4; q++) acc[mt][nt][q] = 0.f;

    const int srow = tid >> 3;          // 0..31, +32 per it
    const int sq = tid & 7;             // k-quad (4 k values)

    // ---- prologue: load + stage chunk 0 into buf0 ----
    float4 pa[4];
#pragma unroll
    for (int it = 0; it < 4; it++) {
        int row = it * 32 + srow;
        pa[it] = (bm + row < N_NODES)
                 ? *(const float4*)&A1[(long long)(bm + row) * 128 + sq * 4]
                 : make_float4(0.f, 0.f, 0.f, 0.f);
    }
#pragma unroll
    for (int it = 0; it < 4; it++) {
        int row = it * 32 + srow;
        uint32_t off = (uint32_t)(row * RSTR + sq * 8);
        float4 v = pa[it];
        uint32_t h01, l01, h23, l23;
        split2(v.x, v.y, h01, l01);
        split2(v.z, v.w, h23, l23);
        *(uint2*)(smc + SM_AH + off) = make_uint2(h01, h23);
        *(uint2*)(smc + SM_AL + off) = make_uint2(l01, l23);
        *(uint2*)(smc + SM_BH + off) = *(const uint2*)&Wt[row * 64 + sq * 2];
        *(uint2*)(smc + SM_BL + off) = *(const uint2*)&Wt[8192 + row * 64 + sq * 2];
    }
    __syncthreads();
    // prefetch chunk 1's A
#pragma unroll
    for (int it = 0; it < 4; it++) {
        int row = it * 32 + srow;
        pa[it] = (bm + row < N_NODES)
                 ? *(const float4*)&A1[(long long)(bm + row) * 128 + 32 + sq * 4]
                 : make_float4(0.f, 0.f, 0.f, 0.f);
    }

    // ldmatrix lane addressing
    const int aRow16 = lane & 15;
    const uint32_t aSel = (uint32_t)(lane >> 4) * 16u;
    const int bRow = lane & 7;
    const uint32_t bK = (uint32_t)((lane >> 3) & 1) * 16u;

#pragma unroll
    for (int c = 0; c < 8; c++) {
        const uint32_t curB = (uint32_t)(c & 1) * BUFSZ;
        const uint32_t nxtB = curB ^ BUFSZ;

        // ---- stage chunk c+1 into buf[nxt] using prefetched pa ----
        if (c < 7) {
            const int cn = c + 1;
            const int k0w = (cn & 3) * 16;
            const uint32_t* Whi = Wt + ((cn >> 2) * 2) * 8192;
            const uint32_t* Wlo = Whi + 8192;
#pragma unroll
            for (int it = 0; it < 4; it++) {
                int row = it * 32 + srow;
                uint32_t off = nxtB + (uint32_t)(row * RSTR + sq * 8);
                float4 v = pa[it];
                uint32_t h01, l01, h23, l23;
                split2(v.x, v.y, h01, l01);
                split2(v.z, v.w, h23, l23);
                *(uint2*)(smc + SM_AH + off) = make_uint2(h01, h23);
                *(uint2*)(smc + SM_AL + off) = make_uint2(l01, l23);
                *(uint2*)(smc + SM_BH + off) = *(const uint2*)&Whi[row * 64 + k0w + sq * 2];
                *(uint2*)(smc + SM_BL + off) = *(const uint2*)&Wlo[row * 64 + k0w + sq * 2];
            }
        }
        // ---- prefetch chunk c+2's A (loads in flight during compute) ----
        if (c < 6) {
            const int cn2 = c + 2;
            const float* An = (cn2 < 4) ? A1 : A2;
            const int k0n = (cn2 & 3) * 32;
#pragma unroll
            for (int it = 0; it < 4; it++) {
                int row = it * 32 + srow;
                pa[it] = (bm + row < N_NODES)
                         ? *(const float4*)&An[(long long)(bm + row) * 128 + k0n + sq * 4]
                         : make_float4(0.f, 0.f, 0.f, 0.f);
            }
        }

        // ---- compute chunk c from buf[cur] ----
#pragma unroll
        for (int ks = 0; ks < 2; ks++) {
            uint32_t ah[2][4], al[2][4];
#pragma unroll
            for (int mt = 0; mt < 2; mt++) {
                uint32_t base = sbase + curB + (uint32_t)((mbase + mt * 16 + aRow16) * RSTR)
                              + (uint32_t)ks * 32u + aSel;
                ldsm_x4(ah[mt], base + SM_AH);
                ldsm_x4(al[mt], base + SM_AL);
            }
#pragma unroll
            for (int nt = 0; nt < 8; nt++) {
                uint32_t bb = sbase + curB + (uint32_t)((nbase + nt * 8 + bRow) * RSTR)
                            + (uint32_t)ks * 32u + bK;
                uint32_t bh[2], bl[2];
                ldsm_x2(bh, bb + SM_BH);
                ldsm_x2(bl, bb + SM_BL);
#pragma unroll
                for (int mt = 0; mt < 2; mt++) {
                    mma_bf16(acc[mt][nt], ah[mt], bh[0], bh[1]);
                    mma_bf16(acc[mt][nt], ah[mt], bl[0], bl[1]);
                    mma_bf16(acc[mt][nt], al[mt], bh[0], bh[1]);
                }
            }
        }
        __syncthreads();
    }

    // ---- epilogue: bias + relu, float2 stores ----
#pragma unroll
    for (int mt = 0; mt < 2; mt++) {
        int row0 = bm + mbase + mt * 16 + g;
        int row1 = row0 + 8;
#pragma unroll
        for (int nt = 0; nt < 8; nt++) {
            int col = nbase + nt * 8 + 2 * tg;
            float b0 = bias[col];
            float b1 = bias[col + 1];
            if (row0 < N_NODES) {
                float2 o;
                o.x = fmaxf(acc[mt][nt][0] + b0, 0.f);
                o.y = fmaxf(acc[mt][nt][1] + b1, 0.f);
                *(float2*)&C[(long long)row0 * 128 + col] = o;
            }
            if (row1 < N_NODES) {
                float2 o;
                o.x = fmaxf(acc[mt][nt][2] + b0, 0.f);
                o.y = fmaxf(acc[mt][nt][3] + b1, 0.f);
                *(float2*)&C[(long long)row1 * 128 + col] = o;
            }
        }
    }
}

// ---------------- pooling / SNN / fusion ----------------
__global__ void k_zero_pool() {
    int i = blockIdx.x * blockDim.x + threadIdx.x;
    if (i < N_GRAPHS * D) g_pool[i] = 0.f;
    if (i < N_GRAPHS) g_cnt[i] = 0.f;
}

#define PCHUNK 256
__global__ void k_pool(const float* __restrict__ h, const void* bt) {
    int blk = blockIdx.x;
    int f = threadIdx.x;
    int start = blk * PCHUNK;
    if (start >= N_NODES) return;
    int end = start + PCHUNK;
    if (end > N_NODES) end = N_NODES;
    int is64 = g_flags[1];
    int cur = ld_idx(bt, start, is64);
    float s = 0.f, c = 0.f;
    for (int n = start; n < end; n++) {
        int g = ld_idx(bt, n, is64);
        if (g != cur) {
            atomicAdd(&g_pool[cur * D + f], s);
            if (f == 0) atomicAdd(&g_cnt[cur], c);
            s = 0.f; c = 0.f; cur = g;
        }
        s += h[(long long)n * D + f];
        c += 1.f;
    }
    atomicAdd(&g_pool[cur * D + f], s);
    if (f == 0) atomicAdd(&g_cnt[cur], c);
}

__global__ void k_snn1(const float* __restrict__ x, const float* __restrict__ w1,
                       const float* __restrict__ b1) {
    int g = blockIdx.x;
    int t = threadIdx.x;   // 256
    __shared__ float xs[SNN_IN];
    for (int i = t; i < SNN_IN; i += 256) xs[i] = x[g * SNN_IN + i];
    __syncthreads();
    for (int j = t; j < SNN_HID; j += 256) {
        float a = b1[j];
        for (int k = 0; k < SNN_IN; k++)
            a += xs[k] * w1[k * SNN_HID + j];
        g_snnh[g * SNN_HID + j] = fmaxf(a, 0.f);
    }
}

__global__ void k_final(const float* __restrict__ lin_w, const float* __restrict__ lin_b,
                        const float* __restrict__ w2, const float* __restrict__ b2,
                        const float* __restrict__ fuse_w, const float* __restrict__ fuse_b,
                        float* __restrict__ out) {
    int g = blockIdx.x;
    int t = threadIdx.x;   // 128
    __shared__ float mean[D];
    __shared__ float red[128];
    __shared__ float snl[N_CLASSES], gnl[N_CLASSES];
    float cnt = fmaxf(g_cnt[g], 1.f);
    mean[t] = g_pool[g * D + t] / cnt;
    __syncthreads();
    for (int c = 0; c < N_CLASSES; c++) {
        red[t] = mean[t] * lin_w[t * N_CLASSES + c];
        for (int off = 64; off > 0; off >>= 1) {
            __syncthreads();
            if (t < off) red[t] += red[t + off];
        }
        __syncthreads();
        if (t == 0) gnl[c] = red[0] + lin_b[c];
        __syncthreads();
    }
    for (int c = 0; c < N_CLASSES; c++) {
        float p = 0.f;
        for (int k = t; k < SNN_HID; k += 128)
            p += g_snnh[g * SNN_HID + k] * w2[k * N_CLASSES + c];
        red[t] = p;
        for (int off = 64; off > 0; off >>= 1) {
            __syncthreads();
            if (t < off) red[t] += red[t + off];
        }
        __syncthreads();
        if (t == 0) snl[c] = SNN_BETA * (red[0] + b2[c]);
        __syncthreads();
    }
    if (t < N_CLASSES) {
        float o = fuse_b[t];
        for (int j = 0; j < N_CLASSES; j++) {
            o += snl[j] * fuse_w[j * N_CLASSES + t];
            o += gnl[j] * fuse_w[(N_CLASSES + j) * N_CLASSES + t];
        }
        out[g * N_CLASSES + t] = o;
    }
}

// ---------------- launch ----------------
extern "C" void kernel_launch(void* const* d_in, const int* in_sizes, int n_in,
                              void* d_out, int out_size) {
    const float* snn_x  = (const float*)d_in[0];
    const float* x      = (const float*)d_in[1];
    const void*  ei     = d_in[2];
    const void*  bt     = d_in[3];
    const float* snn_w1 = (const float*)d_in[4];
    const float* snn_b1 = (const float*)d_in[5];
    const float* snn_w2 = (const float*)d_in[6];
    const float* snn_b2 = (const float*)d_in[7];
    const float* wrel   = (const float*)d_in[8];
    const float* wroot  = (const float*)d_in[9];
    const float* brel   = (const float*)d_in[10];
    const float* lin_w  = (const float*)d_in[11];
    const float* lin_b  = (const float*)d_in[12];
    const float* fuse_w = (const float*)d_in[13];
    const float* fuse_b = (const float*)d_in[14];
    float* out = (float*)d_out;

    void* p;
    cudaGetSymbolAddress(&p, g_h0);   float* h0  = (float*)p;
    cudaGetSymbolAddress(&p, g_h1);   float* h1  = (float*)p;
    cudaGetSymbolAddress(&p, g_agg);  float* agp = (float*)p;
    cudaGetSymbolAddress(&p, g_wsp);  uint32_t* wsp = (uint32_t*)p;

    cudaFuncSetAttribute(k_gemm_bf16, cudaFuncAttributeMaxDynamicSharedMemorySize, GEMM_SMEM);

    k_detect<<<1, 256>>>((const unsigned int*)ei, (const unsigned int*)bt);
    k_wprep<<<(N_LAYERS * 2 * D * (D / 2) + 255) / 256, 256>>>(wrel, wroot);

    // CSR build (by dst)
    k_zero_counts<<<(N_NODES + 255) / 256, 256>>>();
    k_hist<<<(N_EDGES + 255) / 256, 256>>>(ei);
    const int nsb = (N_NODES + 1023) / 1024;   // 98
    k_scan1<<<nsb, 1024>>>();
    k_scan2<<<1, 1>>>(nsb);
    k_scan3<<<(N_NODES + 255) / 256, 256>>>();
    k_scatter<<<(N_EDGES + 255) / 256, 256>>>(ei);

    // 7 GraphConv layers; layer 0 consumes x directly
    const float* hin = x;
    float* hout = h1;
    const int aggBlocks = (N_NODES * 32 + 255) / 256;
    const int gemmBlocks = (N_NODES + 127) / 128;   // 782
    for (int l = 0; l < N_LAYERS; l++) {
        k_agg<<<aggBlocks, 256>>>(hin, agp);
        k_gemm_bf16<<<gemmBlocks, 256, GEMM_SMEM>>>(agp, hin,
                                                    wsp + (long long)l * 4 * 8192,
                                                    brel + (long long)l * D, hout);
        hin = hout;
        hout = (hout == h1) ? h0 : h1;
    }

    // global mean pool
    k_zero_pool<<<(N_GRAPHS * D + 255) / 256, 256>>>();
    k_pool<<<(N_NODES + PCHUNK - 1) / PCHUNK, 128>>>(hin, bt);

    // SNN + fusion
    k_snn1<<<N_GRAPHS, 256>>>(snn_x, snn_w1, snn_b1);
    k_final<<<N_GRAPHS, 128>>>(lin_w, lin_b, snn_w2, snn_b2, fuse_w, fuse_b, out);
}